// round 2
// baseline (speedup 1.0000x reference)
#include <cuda_runtime.h>

#define BB_ 4
#define LL_ 512
#define HH_ 768
#define HS_ 64
#define OUT_ 16
#define NTOK (BB_*LL_)          // 2048
#define NPAIR ((LL_*(LL_+1))/2) // 131328

// Scratch (no allocations allowed; static device globals)
__device__ float g_q[NTOK*HS_];
__device__ float g_k[NTOK*HS_];
__device__ float g_A[NTOK*OUT_];
__device__ float g_C[NTOK*OUT_];

// ---------------------------------------------------------------------------
// Kernel 1: q|k projection.  GEMM: M=2048 tokens, N=128 (q cols 0..63, k cols
// 64..127), K=768.  BM=16, BN=128, BK=16, 128 threads, TM=4 x TN=4 per thread.
// ---------------------------------------------------------------------------
__global__ __launch_bounds__(128) void proj_kernel(
    const float* __restrict__ x,
    const float* __restrict__ Wq, const float* __restrict__ bq,
    const float* __restrict__ Wk, const float* __restrict__ bk)
{
    __shared__ __align__(16) float Xs[16][16];    // [k][m]
    __shared__ __align__(16) float Ws[16][128];   // [k][n]

    const int tid = threadIdx.x;
    const int m0  = blockIdx.x * 16;
    const int tx  = tid & 31;   // n-group: n = 4*tx
    const int ty  = tid >> 5;   // m-group: m = m0 + 4*ty + r

    float acc[4][4];
    #pragma unroll
    for (int r = 0; r < 4; r++)
        #pragma unroll
        for (int c = 0; c < 4; c++) acc[r][c] = 0.f;

    // W-tile loader mapping (constant per thread)
    const int wj  = tid >> 3;          // row in tile: 0..15
    const int wn0 = (tid & 7) * 16;    // col chunk: 0,16,...,112  (stays in one half)
    const float* wsrc = (wn0 < 64) ? (Wq + wn0) : (Wk + (wn0 - 64));

    for (int k0 = 0; k0 < HH_; k0 += 16) {
        // Load X tile (transposed into [k][m])
        #pragma unroll
        for (int e = tid; e < 256; e += 128) {
            int m = e >> 4, kk = e & 15;
            Xs[kk][m] = x[(m0 + m) * HH_ + k0 + kk];
        }
        // Load W tile
        {
            const float4* s4 = (const float4*)(wsrc + (size_t)(k0 + wj) * HS_);
            float4* d4 = (float4*)(&Ws[wj][wn0]);
            d4[0] = s4[0]; d4[1] = s4[1]; d4[2] = s4[2]; d4[3] = s4[3];
        }
        __syncthreads();

        #pragma unroll
        for (int kk = 0; kk < 16; kk++) {
            float4 xv = *(const float4*)(&Xs[kk][ty * 4]);   // broadcast in warp
            float4 wv = *(const float4*)(&Ws[kk][tx * 4]);
            float xa[4] = {xv.x, xv.y, xv.z, xv.w};
            float wa[4] = {wv.x, wv.y, wv.z, wv.w};
            #pragma unroll
            for (int r = 0; r < 4; r++)
                #pragma unroll
                for (int c = 0; c < 4; c++)
                    acc[r][c] += xa[r] * wa[c];
        }
        __syncthreads();
    }

    // Epilogue: add bias, scatter into g_q / g_k
    const int n = tx * 4;
    float4 bias;
    if (n < 64) bias = *(const float4*)(bq + n);
    else        bias = *(const float4*)(bk + (n - 64));

    #pragma unroll
    for (int r = 0; r < 4; r++) {
        int m = m0 + ty * 4 + r;
        float4 v;
        v.x = acc[r][0] + bias.x; v.y = acc[r][1] + bias.y;
        v.z = acc[r][2] + bias.z; v.w = acc[r][3] + bias.w;
        if (n < 64) *(float4*)(g_q + m * HS_ + n)        = v;
        else        *(float4*)(g_k + m * HS_ + (n - 64)) = v;
    }
}

// ---------------------------------------------------------------------------
// Kernel 2: per-token A and C vectors (16 wide).
//   A[m,o] = sum_h q[m,h] * Wb[h,o]                       (W1 rows   0..63)
//   C[m,o] = sum_h q[m,h]*Wb[128+h,o]
//          + sum_h k[m,h]*(Wb[64+h,o]+Wb[192+h,o]) + bb[o]
// ---------------------------------------------------------------------------
__global__ __launch_bounds__(256) void ac_kernel(
    const float* __restrict__ Wb, const float* __restrict__ bb)
{
    int idx = blockIdx.x * blockDim.x + threadIdx.x;
    if (idx >= NTOK * OUT_) return;
    int m = idx >> 4;
    int o = idx & 15;

    const float* q = g_q + m * HS_;
    const float* k = g_k + m * HS_;

    float a = 0.f;
    float c = bb[o];
    #pragma unroll
    for (int h = 0; h < HS_; h++) {
        float qv = q[h];
        float kv = k[h];
        a += qv * Wb[h * 16 + o];
        c += qv * Wb[(128 + h) * 16 + o];
        c += kv * (Wb[(64 + h) * 16 + o] + Wb[(192 + h) * 16 + o]);
    }
    g_A[idx] = a;
    g_C[idx] = c;
}

// ---------------------------------------------------------------------------
// Kernel 3: pair kernel.  Block = (batch b, 8 consecutive start-rows i0..i0+7).
// Thread handles column j (grid-stride from i0), loads k_j once, computes 8
// dots against the SMEM-resident q rows, writes 8x16 outputs.
// Pair offset: poff(i) = i*L - i*(i-1)/2 ; p = poff(i) + (j - i).
// ---------------------------------------------------------------------------
__global__ __launch_bounds__(256) void pair_kernel(float* __restrict__ out)
{
    const int b  = blockIdx.y;
    const int i0 = blockIdx.x * 8;
    const int tid = threadIdx.x;

    __shared__ __align__(16) float qs[8 * HS_];    // 2 KB
    __shared__ __align__(16) float As[8 * OUT_];   // 512 B

    const int tokbase = b * LL_ + i0;
    qs[tid]       = g_q[tokbase * HS_ + tid];
    qs[tid + 256] = g_q[tokbase * HS_ + 256 + tid];
    if (tid < 128) As[tid] = g_A[tokbase * OUT_ + tid];
    __syncthreads();

    for (int j = i0 + tid; j < LL_; j += 256) {
        // Load k_j row (256B) and C_j (64B) into registers
        const float4* k4 = (const float4*)(g_k + (size_t)(b * LL_ + j) * HS_);
        float4 kv[16];
        #pragma unroll
        for (int t = 0; t < 16; t++) kv[t] = k4[t];

        const float4* c4 = (const float4*)(g_C + (size_t)(b * LL_ + j) * OUT_);
        float4 cv[4];
        #pragma unroll
        for (int t = 0; t < 4; t++) cv[t] = c4[t];

        #pragma unroll
        for (int ii = 0; ii < 8; ii++) {
            const int i = i0 + ii;
            if (j < i) continue;

            const float4* q4 = (const float4*)(qs + ii * HS_);
            float dx = 0.f, dy = 0.f, dz = 0.f, dw = 0.f;
            #pragma unroll
            for (int t = 0; t < 16; t++) {
                float4 qv = q4[t];
                dx += qv.x * kv[t].x;
                dy += qv.y * kv[t].y;
                dz += qv.z * kv[t].z;
                dw += qv.w * kv[t].w;
            }
            const float dot = (dx + dy) + (dz + dw);

            const int poff = i * LL_ - (i * (i - 1)) / 2;
            const int p = b * NPAIR + poff + (j - i);
            float4* o4 = (float4*)(out + (size_t)p * OUT_);
            const float4* a4 = (const float4*)(As + ii * OUT_);
            #pragma unroll
            for (int t = 0; t < 4; t++) {
                float4 av = a4[t];
                float4 r;
                r.x = dot + av.x + cv[t].x;
                r.y = dot + av.y + cv[t].y;
                r.z = dot + av.z + cv[t].z;
                r.w = dot + av.w + cv[t].w;
                o4[t] = r;
            }
        }
    }
}

// ---------------------------------------------------------------------------
extern "C" void kernel_launch(void* const* d_in, const int* in_sizes, int n_in,
                              void* d_out, int out_size)
{
    const float* x  = (const float*)d_in[0];
    const float* Wq = (const float*)d_in[1];
    const float* bq = (const float*)d_in[2];
    const float* Wk = (const float*)d_in[3];
    const float* bk = (const float*)d_in[4];
    const float* Wb = (const float*)d_in[5];
    const float* bb = (const float*)d_in[6];
    float* out = (float*)d_out;

    proj_kernel<<<NTOK / 16, 128>>>(x, Wq, bq, Wk, bk);
    ac_kernel<<<(NTOK * OUT_ + 255) / 256, 256>>>(Wb, bb);
    pair_kernel<<<dim3(LL_ / 8, BB_), 256>>>(out);
}

// round 3
// speedup vs baseline: 1.0410x; 1.0410x over previous
#include <cuda_runtime.h>

#define BB_ 4
#define LL_ 512
#define HH_ 768
#define HS_ 64
#define OUT_ 16
#define NTOK (BB_*LL_)          // 2048
#define NPAIR ((LL_*(LL_+1))/2) // 131328
#define TILES (HH_/32)          // 24

// Scratch (no allocations allowed; static device globals)
__device__ float g_q[NTOK*HS_];
__device__ float g_k[NTOK*HS_];
__device__ float g_A[NTOK*OUT_];
__device__ float g_C[NTOK*OUT_];

// ---------------------------------------------------------------------------
// Kernel 1: q|k projection + fused A/C epilogue.
// GEMM: M=2048, N=128 (q cols 0..63 | k cols 64..127), K=768.
// BM=16, BN=128, BK=32, 256 threads (8 warps), 2x4 per-thread micro-tile,
// register-prefetch double-pipelining.
// Epilogue (block owns its 16 complete q|k rows):
//   A[m,o] = sum_h q[m,h]*Wb[h,o]
//   C[m,o] = sum_h q[m,h]*Wb[128+h,o] + k[m,h]*(Wb[64+h,o]+Wb[192+h,o]) + bb[o]
// ---------------------------------------------------------------------------
__global__ __launch_bounds__(256) void proj_kernel(
    const float* __restrict__ x,
    const float* __restrict__ Wq, const float* __restrict__ bq,
    const float* __restrict__ Wk, const float* __restrict__ bk,
    const float* __restrict__ Wb, const float* __restrict__ bb)
{
    __shared__ __align__(16) float Xs[16][32];     // [m][kk]  2 KB
    __shared__ __align__(16) float Ws[32][128];    // [kk][n] 16 KB (reused as S[16][128] in epilogue)
    __shared__ __align__(16) float WBs[256 * 16];  // Wb copy 16 KB

    const int tid = threadIdx.x;
    const int m0  = blockIdx.x * 16;
    const int tx  = tid & 31;   // n = 4*tx
    const int ty  = tid >> 5;   // m = 2*ty + r

    // Stage Wb into SMEM (used only in epilogue; latency fully hidden)
    {
        const float4* src = (const float4*)Wb;
        float4* dst = (float4*)WBs;
        #pragma unroll
        for (int t = 0; t < 4; t++) dst[tid + 256 * t] = src[tid + 256 * t];
    }

    // Loader mappings
    const int xm = tid >> 3;             // 0..31 (only tid<128 loads X)
    const int xk = (tid & 7) * 4;        // 0..28
    const int wkk = tid >> 3;            // 0..31
    const int wc0 = (tid & 7) * 16;      // 0,16,...,112 (stays within one half)
    const float* wsrc = (wc0 < 64) ? (Wq + wc0) : (Wk + (wc0 - 64));

    float4 xr;
    float4 wr0, wr1, wr2, wr3;

    // Preload tile 0 into regs, then SMEM
    if (tid < 128) xr = *(const float4*)(x + (size_t)(m0 + xm) * HH_ + xk);
    {
        const float4* s4 = (const float4*)(wsrc + (size_t)wkk * HS_);
        wr0 = s4[0]; wr1 = s4[1]; wr2 = s4[2]; wr3 = s4[3];
    }
    if (tid < 128) *(float4*)(&Xs[xm][xk]) = xr;
    {
        float4* d4 = (float4*)(&Ws[wkk][wc0]);
        d4[0] = wr0; d4[1] = wr1; d4[2] = wr2; d4[3] = wr3;
    }
    __syncthreads();

    float acc[2][4];
    #pragma unroll
    for (int r = 0; r < 2; r++)
        #pragma unroll
        for (int c = 0; c < 4; c++) acc[r][c] = 0.f;

    for (int t = 0; t < TILES; t++) {
        // Prefetch next tile into registers while computing current
        if (t + 1 < TILES) {
            const int k0n = (t + 1) * 32;
            if (tid < 128) xr = *(const float4*)(x + (size_t)(m0 + xm) * HH_ + k0n + xk);
            const float4* s4 = (const float4*)(wsrc + (size_t)(k0n + wkk) * HS_);
            wr0 = s4[0]; wr1 = s4[1]; wr2 = s4[2]; wr3 = s4[3];
        }

        #pragma unroll
        for (int kk = 0; kk < 32; kk++) {
            float4 wv = *(const float4*)(&Ws[kk][tx * 4]);  // conflict-free LDS.128
            float x0 = Xs[ty * 2 + 0][kk];                  // warp broadcast
            float x1 = Xs[ty * 2 + 1][kk];
            acc[0][0] += x0 * wv.x; acc[0][1] += x0 * wv.y;
            acc[0][2] += x0 * wv.z; acc[0][3] += x0 * wv.w;
            acc[1][0] += x1 * wv.x; acc[1][1] += x1 * wv.y;
            acc[1][2] += x1 * wv.z; acc[1][3] += x1 * wv.w;
        }
        __syncthreads();
        if (t + 1 < TILES) {
            if (tid < 128) *(float4*)(&Xs[xm][xk]) = xr;
            float4* d4 = (float4*)(&Ws[wkk][wc0]);
            d4[0] = wr0; d4[1] = wr1; d4[2] = wr2; d4[3] = wr3;
        }
        __syncthreads();
    }

    // ---- Epilogue: bias add, global q/k store, stash S[m][0..127] in Ws ----
    const int n = tx * 4;
    float4 bias = (n < 64) ? *(const float4*)(bq + n) : *(const float4*)(bk + (n - 64));

    #pragma unroll
    for (int r = 0; r < 2; r++) {
        const int m = ty * 2 + r;
        float4 v;
        v.x = acc[r][0] + bias.x; v.y = acc[r][1] + bias.y;
        v.z = acc[r][2] + bias.z; v.w = acc[r][3] + bias.w;
        if (n < 64) *(float4*)(g_q + (size_t)(m0 + m) * HS_ + n)        = v;
        else        *(float4*)(g_k + (size_t)(m0 + m) * HS_ + (n - 64)) = v;
        *(float4*)(&Ws[m][n]) = v;   // S row: [0..63]=q, [64..127]=k
    }
    __syncthreads();

    // ---- Fused A/C: thread -> (m = tid>>4, o = tid&15) ----
    {
        const int am = tid >> 4;
        const int ao = tid & 15;
        const float* S = &Ws[am][0];
        float a = 0.f;
        float c = bb[ao];
        #pragma unroll
        for (int h = 0; h < HS_; h++) {
            float qv = S[h];
            float kv = S[64 + h];
            a += qv * WBs[h * 16 + ao];
            c += qv * WBs[(128 + h) * 16 + ao];
            c += kv * (WBs[(64 + h) * 16 + ao] + WBs[(192 + h) * 16 + ao]);
        }
        g_A[(m0 + am) * OUT_ + ao] = a;
        g_C[(m0 + am) * OUT_ + ao] = c;
    }
}

// ---------------------------------------------------------------------------
// Kernel 2: pair kernel.  Block = (batch b, 16 consecutive start-rows).
// Thread handles column j, loads k_j once, dots against 16 SMEM q rows,
// writes 16x16 outputs (64B contiguous per pair, coalesced across warp).
// p = b*NPAIR + i*L - i*(i-1)/2 + (j - i)
// ---------------------------------------------------------------------------
__global__ __launch_bounds__(256) void pair_kernel(float* __restrict__ out)
{
    const int b   = blockIdx.y;
    const int i0  = blockIdx.x * 16;
    const int tid = threadIdx.x;

    __shared__ __align__(16) float qs[16 * HS_];   // 4 KB
    __shared__ __align__(16) float As[16 * OUT_];  // 1 KB

    const int tokbase = b * LL_ + i0;
    ((float4*)qs)[tid] = ((const float4*)(g_q + (size_t)tokbase * HS_))[tid];
    As[tid] = g_A[tokbase * OUT_ + tid];
    __syncthreads();

    for (int j = i0 + tid; j < LL_; j += 256) {
        const float4* k4 = (const float4*)(g_k + (size_t)(b * LL_ + j) * HS_);
        float4 kv[16];
        #pragma unroll
        for (int t = 0; t < 16; t++) kv[t] = k4[t];

        const float4* c4 = (const float4*)(g_C + (size_t)(b * LL_ + j) * OUT_);
        float4 cv[4];
        #pragma unroll
        for (int t = 0; t < 4; t++) cv[t] = c4[t];

        #pragma unroll
        for (int ii = 0; ii < 16; ii++) {
            const int i = i0 + ii;
            if (j < i) continue;

            const float4* q4 = (const float4*)(qs + ii * HS_);
            float dx = 0.f, dy = 0.f, dz = 0.f, dw = 0.f;
            #pragma unroll
            for (int t = 0; t < 16; t++) {
                float4 qv = q4[t];
                dx += qv.x * kv[t].x;
                dy += qv.y * kv[t].y;
                dz += qv.z * kv[t].z;
                dw += qv.w * kv[t].w;
            }
            const float dot = (dx + dy) + (dz + dw);

            const int poff = i * LL_ - (i * (i - 1)) / 2;
            const int p = b * NPAIR + poff + (j - i);
            float4* o4 = (float4*)(out + (size_t)p * OUT_);
            const float4* a4 = (const float4*)(As + ii * OUT_);
            #pragma unroll
            for (int t = 0; t < 4; t++) {
                float4 av = a4[t];
                float4 r;
                r.x = dot + av.x + cv[t].x;
                r.y = dot + av.y + cv[t].y;
                r.z = dot + av.z + cv[t].z;
                r.w = dot + av.w + cv[t].w;
                o4[t] = r;
            }
        }
    }
}

// ---------------------------------------------------------------------------
extern "C" void kernel_launch(void* const* d_in, const int* in_sizes, int n_in,
                              void* d_out, int out_size)
{
    const float* x  = (const float*)d_in[0];
    const float* Wq = (const float*)d_in[1];
    const float* bq = (const float*)d_in[2];
    const float* Wk = (const float*)d_in[3];
    const float* bk = (const float*)d_in[4];
    const float* Wb = (const float*)d_in[5];
    const float* bb = (const float*)d_in[6];
    float* out = (float*)d_out;

    proj_kernel<<<NTOK / 16, 256>>>(x, Wq, bq, Wk, bk, Wb, bb);
    pair_kernel<<<dim3(LL_ / 16, BB_), 256>>>(out);
}

// round 4
// speedup vs baseline: 1.0745x; 1.0322x over previous
#include <cuda_runtime.h>

#define BB_ 4
#define LL_ 512
#define HH_ 768
#define HS_ 64
#define OUT_ 16
#define NTOK (BB_*LL_)          // 2048
#define NPAIR ((LL_*(LL_+1))/2) // 131328
#define KHALF (HH_/2)           // 384
#define TILES2 (KHALF/32)       // 12

typedef unsigned long long ull;

// f32x2 packed-fp32 helpers (FFMA2 path — PTX-only per SASS_QUICKREF)
__device__ __forceinline__ void fma2(ull& d, ull a, ull b) {
    asm("fma.rn.f32x2 %0, %1, %2, %0;" : "+l"(d) : "l"(a), "l"(b));
}
__device__ __forceinline__ ull dup2(float x) {
    ull r; asm("mov.b64 %0, {%1, %1};" : "=l"(r) : "f"(x)); return r;
}
__device__ __forceinline__ float2 un2(ull v) {
    float2 f; asm("mov.b64 {%0, %1}, %2;" : "=f"(f.x), "=f"(f.y) : "l"(v)); return f;
}

// Scratch (static device globals; no allocations allowed)
__device__ float g_part[2][NTOK * 128];   // split-K partials: [m][n], n: 0..63=q, 64..127=k
__device__ float g_q[NTOK * HS_];
__device__ float g_k[NTOK * HS_];
__device__ float g_A[NTOK * OUT_];
__device__ float g_C[NTOK * OUT_];

// ---------------------------------------------------------------------------
// Kernel 1: q|k projection, split-K=2, FFMA2 inner loop, no bias (deferred).
// GEMM: M=2048, N=128 (q|k), K=384 per block.y.  BM=16, BN=128, BK=32,
// 256 threads, 2x4 per-thread micro-tile as 2x2 f32x2 accumulators.
// ---------------------------------------------------------------------------
__global__ __launch_bounds__(256) void proj_kernel(
    const float* __restrict__ x,
    const float* __restrict__ Wq, const float* __restrict__ Wk)
{
    __shared__ __align__(16) float Xs[16][32];     // [m][kk]
    __shared__ __align__(16) float Ws[32][128];    // [kk][n]

    const int tid   = threadIdx.x;
    const int m0    = blockIdx.x * 16;
    const int kbase = blockIdx.y * KHALF;
    const int tx    = tid & 31;   // n = 4*tx
    const int ty    = tid >> 5;   // rows 2*ty, 2*ty+1

    // Loader mappings
    const int xm  = tid >> 3;            // 0..31 (only tid<128 loads X)
    const int xk  = (tid & 7) * 4;
    const int wkk = tid >> 3;            // 0..31
    const int wc0 = (tid & 7) * 16;      // stays within one half
    const float* wsrc = (wc0 < 64) ? (Wq + wc0) : (Wk + (wc0 - 64));

    float4 xr; float4 wr0, wr1, wr2, wr3;

    // Preload tile 0
    if (tid < 128) xr = *(const float4*)(x + (size_t)(m0 + xm) * HH_ + kbase + xk);
    {
        const float4* s4 = (const float4*)(wsrc + (size_t)(kbase + wkk) * HS_);
        wr0 = s4[0]; wr1 = s4[1]; wr2 = s4[2]; wr3 = s4[3];
    }
    if (tid < 128) *(float4*)(&Xs[xm][xk]) = xr;
    {
        float4* d4 = (float4*)(&Ws[wkk][wc0]);
        d4[0] = wr0; d4[1] = wr1; d4[2] = wr2; d4[3] = wr3;
    }
    __syncthreads();

    ull a00 = 0ull, a01 = 0ull, a10 = 0ull, a11 = 0ull;

    for (int t = 0; t < TILES2; t++) {
        if (t + 1 < TILES2) {
            const int k0n = kbase + (t + 1) * 32;
            if (tid < 128) xr = *(const float4*)(x + (size_t)(m0 + xm) * HH_ + k0n + xk);
            const float4* s4 = (const float4*)(wsrc + (size_t)(k0n + wkk) * HS_);
            wr0 = s4[0]; wr1 = s4[1]; wr2 = s4[2]; wr3 = s4[3];
        }

        #pragma unroll
        for (int kk = 0; kk < 32; kk++) {
            const ull* w2 = (const ull*)(&Ws[kk][tx * 4]);
            ull w0 = w2[0], w1 = w2[1];
            ull x0 = dup2(Xs[ty * 2 + 0][kk]);
            ull x1 = dup2(Xs[ty * 2 + 1][kk]);
            fma2(a00, x0, w0); fma2(a01, x0, w1);
            fma2(a10, x1, w0); fma2(a11, x1, w1);
        }
        __syncthreads();
        if (t + 1 < TILES2) {
            if (tid < 128) *(float4*)(&Xs[xm][xk]) = xr;
            float4* d4 = (float4*)(&Ws[wkk][wc0]);
            d4[0] = wr0; d4[1] = wr1; d4[2] = wr2; d4[3] = wr3;
        }
        __syncthreads();
    }

    // Store partials (no bias)
    float* dst = g_part[blockIdx.y];
    {
        float2 lo = un2(a00), hi = un2(a01);
        float4 v = make_float4(lo.x, lo.y, hi.x, hi.y);
        *(float4*)(dst + (size_t)(m0 + ty * 2 + 0) * 128 + tx * 4) = v;
    }
    {
        float2 lo = un2(a10), hi = un2(a11);
        float4 v = make_float4(lo.x, lo.y, hi.x, hi.y);
        *(float4*)(dst + (size_t)(m0 + ty * 2 + 1) * 128 + tx * 4) = v;
    }
}

// ---------------------------------------------------------------------------
// Kernel 2: combine split-K partials + bias -> g_q/g_k, then fused A/C.
// Block = 16 tokens, 256 threads, grid 128.
//   A[m,o] = sum_h q[m,h]*Wb[h,o]
//   C[m,o] = sum_h q[m,h]*Wb[128+h,o] + k[m,h]*(Wb[64+h,o]+Wb[192+h,o]) + bb[o]
// ---------------------------------------------------------------------------
__global__ __launch_bounds__(256) void combine_kernel(
    const float* __restrict__ bq, const float* __restrict__ bk,
    const float* __restrict__ Wb, const float* __restrict__ bb)
{
    __shared__ __align__(16) float S[16][128];      // combined q|k rows
    __shared__ __align__(16) float WBs[256 * 16];   // Wb copy

    const int tid = threadIdx.x;
    const int m0  = blockIdx.x * 16;

    // Stage Wb
    {
        const float4* src = (const float4*)Wb;
        float4* dst = (float4*)WBs;
        #pragma unroll
        for (int t = 0; t < 4; t++) dst[tid + 256 * t] = src[tid + 256 * t];
    }

    // Combine: 16 rows x 128 cols = 512 float4; thread handles 2 float4
    const size_t base4 = (size_t)m0 * 32;   // float4 index of block base
    #pragma unroll
    for (int e = 0; e < 2; e++) {
        const int idx = tid + 256 * e;
        const int m   = idx >> 5;         // 0..15
        const int c4  = idx & 31;         // float4 col
        const int n   = c4 * 4;
        float4 v0 = ((const float4*)g_part[0])[base4 + idx];
        float4 v1 = ((const float4*)g_part[1])[base4 + idx];
        float4 bias = (n < 64) ? *(const float4*)(bq + n)
                               : *(const float4*)(bk + (n - 64));
        float4 v;
        v.x = v0.x + v1.x + bias.x; v.y = v0.y + v1.y + bias.y;
        v.z = v0.z + v1.z + bias.z; v.w = v0.w + v1.w + bias.w;
        if (n < 64) *(float4*)(g_q + (size_t)(m0 + m) * HS_ + n)        = v;
        else        *(float4*)(g_k + (size_t)(m0 + m) * HS_ + (n - 64)) = v;
        *(float4*)(&S[m][n]) = v;
    }
    __syncthreads();

    // Fused A/C: thread -> (m = tid>>4, o = tid&15)
    {
        const int am = tid >> 4;
        const int ao = tid & 15;
        const float* Sr = &S[am][0];
        float a = 0.f;
        float c = bb[ao];
        #pragma unroll
        for (int h = 0; h < HS_; h++) {
            float qv = Sr[h];
            float kv = Sr[64 + h];
            a += qv * WBs[h * 16 + ao];
            c += qv * WBs[(128 + h) * 16 + ao];
            c += kv * (WBs[(64 + h) * 16 + ao] + WBs[(192 + h) * 16 + ao]);
        }
        g_A[(m0 + am) * OUT_ + ao] = a;
        g_C[(m0 + am) * OUT_ + ao] = c;
    }
}

// ---------------------------------------------------------------------------
// Kernel 3: pair kernel.  TI=4 start-rows per block -> 512 blocks.
// Thread handles column j, loads k_j in two halves (reg pressure), dots
// against 4 SMEM q rows, writes 4x16 outputs (coalesced 64B per pair).
// p = b*NPAIR + i*L - i*(i-1)/2 + (j - i)
// ---------------------------------------------------------------------------
__global__ __launch_bounds__(256) void pair_kernel(float* __restrict__ out)
{
    const int b   = blockIdx.y;
    const int i0  = blockIdx.x * 4;
    const int tid = threadIdx.x;

    __shared__ __align__(16) float qs[4 * HS_];    // 1 KB
    __shared__ __align__(16) float As[4 * OUT_];   // 256 B

    const int tokbase = b * LL_ + i0;
    qs[tid] = g_q[(size_t)tokbase * HS_ + tid];
    if (tid < 64) As[tid] = g_A[tokbase * OUT_ + tid];
    __syncthreads();

    for (int j = i0 + tid; j < LL_; j += 256) {
        const float4* k4 = (const float4*)(g_k + (size_t)(b * LL_ + j) * HS_);

        float4 d[4];
        #pragma unroll
        for (int ii = 0; ii < 4; ii++) d[ii] = make_float4(0.f, 0.f, 0.f, 0.f);

        // half 0: k[0..31]
        {
            float4 kv[8];
            #pragma unroll
            for (int t = 0; t < 8; t++) kv[t] = k4[t];
            #pragma unroll
            for (int ii = 0; ii < 4; ii++) {
                const float4* q4 = (const float4*)(qs + ii * HS_);
                #pragma unroll
                for (int t = 0; t < 8; t++) {
                    float4 qv = q4[t];
                    d[ii].x += qv.x * kv[t].x;
                    d[ii].y += qv.y * kv[t].y;
                    d[ii].z += qv.z * kv[t].z;
                    d[ii].w += qv.w * kv[t].w;
                }
            }
        }
        // half 1: k[32..63]
        {
            float4 kv[8];
            #pragma unroll
            for (int t = 0; t < 8; t++) kv[t] = k4[8 + t];
            #pragma unroll
            for (int ii = 0; ii < 4; ii++) {
                const float4* q4 = (const float4*)(qs + ii * HS_) + 8;
                #pragma unroll
                for (int t = 0; t < 8; t++) {
                    float4 qv = q4[t];
                    d[ii].x += qv.x * kv[t].x;
                    d[ii].y += qv.y * kv[t].y;
                    d[ii].z += qv.z * kv[t].z;
                    d[ii].w += qv.w * kv[t].w;
                }
            }
        }

        float dot[4];
        #pragma unroll
        for (int ii = 0; ii < 4; ii++)
            dot[ii] = (d[ii].x + d[ii].y) + (d[ii].z + d[ii].w);

        const float4* c4 = (const float4*)(g_C + (size_t)(b * LL_ + j) * OUT_);
        float4 cv[4];
        #pragma unroll
        for (int t = 0; t < 4; t++) cv[t] = c4[t];

        #pragma unroll
        for (int ii = 0; ii < 4; ii++) {
            const int i = i0 + ii;
            if (j < i) continue;
            const int poff = i * LL_ - (i * (i - 1)) / 2;
            const int p = b * NPAIR + poff + (j - i);
            float4* o4 = (float4*)(out + (size_t)p * OUT_);
            const float4* a4 = (const float4*)(As + ii * OUT_);
            #pragma unroll
            for (int t = 0; t < 4; t++) {
                float4 av = a4[t];
                float4 r;
                r.x = dot[ii] + av.x + cv[t].x;
                r.y = dot[ii] + av.y + cv[t].y;
                r.z = dot[ii] + av.z + cv[t].z;
                r.w = dot[ii] + av.w + cv[t].w;
                o4[t] = r;
            }
        }
    }
}

// ---------------------------------------------------------------------------
extern "C" void kernel_launch(void* const* d_in, const int* in_sizes, int n_in,
                              void* d_out, int out_size)
{
    const float* x  = (const float*)d_in[0];
    const float* Wq = (const float*)d_in[1];
    const float* bq = (const float*)d_in[2];
    const float* Wk = (const float*)d_in[3];
    const float* bk = (const float*)d_in[4];
    const float* Wb = (const float*)d_in[5];
    const float* bb = (const float*)d_in[6];
    float* out = (float*)d_out;

    proj_kernel<<<dim3(NTOK / 16, 2), 256>>>(x, Wq, Wk);
    combine_kernel<<<NTOK / 16, 256>>>(bq, bk, Wb, bb);
    pair_kernel<<<dim3(LL_ / 4, BB_), 256>>>(out);
}

// round 5
// speedup vs baseline: 1.5607x; 1.4525x over previous
#include <cuda_runtime.h>

#define BB_ 4
#define LL_ 512
#define HH_ 768
#define HS_ 64
#define OUT_ 16
#define NTOK (BB_*LL_)          // 2048
#define NPAIR ((LL_*(LL_+1))/2) // 131328
#define NSPLIT 8
#define KSLICE (HH_/NSPLIT)     // 96
#define BK_ 16
#define TILES (KSLICE/BK_)      // 6
#define BM_ 64

typedef unsigned long long ull;

// f32x2 packed-fp32 helpers (FFMA2 path — PTX-only per SASS_QUICKREF)
__device__ __forceinline__ void fma2(ull& d, ull a, ull b) {
    asm("fma.rn.f32x2 %0, %1, %2, %0;" : "+l"(d) : "l"(a), "l"(b));
}
__device__ __forceinline__ ull dup2(float x) {
    ull r; asm("mov.b64 %0, {%1, %1};" : "=l"(r) : "f"(x)); return r;
}
__device__ __forceinline__ float2 un2(ull v) {
    float2 f; asm("mov.b64 {%0, %1}, %2;" : "=f"(f.x), "=f"(f.y) : "l"(v)); return f;
}

// Scratch (static device globals; no allocations allowed)
__device__ float g_part[NSPLIT][NTOK * 128];  // split-K partials
__device__ float g_q[NTOK * HS_];
__device__ float g_k[NTOK * HS_];
__device__ float g_A[NTOK * OUT_];
__device__ float g_C[NTOK * OUT_];

// ---------------------------------------------------------------------------
// Kernel 1: q|k projection, split-K=8, FFMA2, TM=8 x TN=4 micro-tile.
// GEMM: M=2048, N=128 (q cols | k cols), K=96 per slice.
// BM=64, BN=128, BK=16, 256 threads (32 tx x 8 ty), rows m = ty*8 + r.
// X broadcast loads: Xs[m][kk], whole warp same ty -> same address (free).
// ---------------------------------------------------------------------------
__global__ __launch_bounds__(256, 2) void proj_kernel(
    const float* __restrict__ x,
    const float* __restrict__ Wq, const float* __restrict__ Wk)
{
    __shared__ __align__(16) float Xs[BM_][BK_];    // [m][kk]  4 KB
    __shared__ __align__(16) float Ws[BK_][128];    // [kk][n]  8 KB

    const int tid   = threadIdx.x;
    const int m0    = blockIdx.x * BM_;
    const int kbase = blockIdx.y * KSLICE;
    const int tx    = tid & 31;   // n = 4*tx
    const int ty    = tid >> 5;   // rows ty*8 .. ty*8+7

    // X loader: thread -> one float4.  xm = tid>>2 (0..63), xk = (tid&3)*4
    const int xm = tid >> 2;
    const int xk = (tid & 3) * 4;
    // W loader: 2 float4 per thread. idx=tid+256e: row=idx>>5, col=(idx&31)*4
    const int wrow0 = tid >> 5;          // e=0: rows 0..7
    const int wcol  = (tid & 31) * 4;
    const float* wsrc = (wcol < 64) ? (Wq + wcol) : (Wk + (wcol - 64));

    float4 xr, wr0, wr1;

    // Preload tile 0
    xr  = *(const float4*)(x + (size_t)(m0 + xm) * HH_ + kbase + xk);
    wr0 = *(const float4*)(wsrc + (size_t)(kbase + wrow0) * HS_);
    wr1 = *(const float4*)(wsrc + (size_t)(kbase + wrow0 + 8) * HS_);
    *(float4*)(&Xs[xm][xk]) = xr;
    *(float4*)(&Ws[wrow0][wcol])     = wr0;
    *(float4*)(&Ws[wrow0 + 8][wcol]) = wr1;
    __syncthreads();

    ull acc[8][2];
    #pragma unroll
    for (int r = 0; r < 8; r++) { acc[r][0] = 0ull; acc[r][1] = 0ull; }

    for (int t = 0; t < TILES; t++) {
        if (t + 1 < TILES) {
            const int k0n = kbase + (t + 1) * BK_;
            xr  = *(const float4*)(x + (size_t)(m0 + xm) * HH_ + k0n + xk);
            wr0 = *(const float4*)(wsrc + (size_t)(k0n + wrow0) * HS_);
            wr1 = *(const float4*)(wsrc + (size_t)(k0n + wrow0 + 8) * HS_);
        }

        #pragma unroll
        for (int g = 0; g < BK_ / 4; g++) {       // groups of 4 kk
            float4 xf[8];                          // x[rows][4kk] broadcast loads
            #pragma unroll
            for (int r = 0; r < 8; r++)
                xf[r] = *(const float4*)(&Xs[ty * 8 + r][g * 4]);
            #pragma unroll
            for (int dk = 0; dk < 4; dk++) {
                float4 wv = *(const float4*)(&Ws[g * 4 + dk][tx * 4]);
                ull w0, w1;
                asm("mov.b64 %0, {%1, %2};" : "=l"(w0) : "f"(wv.x), "f"(wv.y));
                asm("mov.b64 %0, {%1, %2};" : "=l"(w1) : "f"(wv.z), "f"(wv.w));
                #pragma unroll
                for (int r = 0; r < 8; r++) {
                    const float* xp = (const float*)&xf[r];
                    ull xd = dup2(xp[dk]);
                    fma2(acc[r][0], xd, w0);
                    fma2(acc[r][1], xd, w1);
                }
            }
        }
        __syncthreads();
        if (t + 1 < TILES) {
            *(float4*)(&Xs[xm][xk]) = xr;
            *(float4*)(&Ws[wrow0][wcol])     = wr0;
            *(float4*)(&Ws[wrow0 + 8][wcol]) = wr1;
            __syncthreads();
        }
    }

    // Store partials
    float* dst = g_part[blockIdx.y];
    #pragma unroll
    for (int r = 0; r < 8; r++) {
        float2 lo = un2(acc[r][0]), hi = un2(acc[r][1]);
        float4 v = make_float4(lo.x, lo.y, hi.x, hi.y);
        *(float4*)(dst + (size_t)(m0 + ty * 8 + r) * 128 + tx * 4) = v;
    }
}

// ---------------------------------------------------------------------------
// Kernel 2: combine 8 split-K partials + bias -> g_q/g_k, then fused A/C.
// Block = 16 tokens, 256 threads, grid 128.
// ---------------------------------------------------------------------------
__global__ __launch_bounds__(256) void combine_kernel(
    const float* __restrict__ bq, const float* __restrict__ bk,
    const float* __restrict__ Wb, const float* __restrict__ bb)
{
    __shared__ __align__(16) float S[16][128];
    __shared__ __align__(16) float WBs[256 * 16];

    const int tid = threadIdx.x;
    const int m0  = blockIdx.x * 16;

    // Stage Wb
    {
        const float4* src = (const float4*)Wb;
        float4* dst = (float4*)WBs;
        #pragma unroll
        for (int t = 0; t < 4; t++) dst[tid + 256 * t] = src[tid + 256 * t];
    }

    // Combine: 16 rows x 32 float4-cols = 512 float4; thread handles 2
    const size_t base4 = (size_t)m0 * 32;
    #pragma unroll
    for (int e = 0; e < 2; e++) {
        const int idx = tid + 256 * e;
        const int m   = idx >> 5;
        const int n   = (idx & 31) * 4;
        float4 v = ((const float4*)g_part[0])[base4 + idx];
        #pragma unroll
        for (int s = 1; s < NSPLIT; s++) {
            float4 p = ((const float4*)g_part[s])[base4 + idx];
            v.x += p.x; v.y += p.y; v.z += p.z; v.w += p.w;
        }
        float4 bias = (n < 64) ? *(const float4*)(bq + n)
                               : *(const float4*)(bk + (n - 64));
        v.x += bias.x; v.y += bias.y; v.z += bias.z; v.w += bias.w;
        if (n < 64) *(float4*)(g_q + (size_t)(m0 + m) * HS_ + n)        = v;
        else        *(float4*)(g_k + (size_t)(m0 + m) * HS_ + (n - 64)) = v;
        *(float4*)(&S[m][n]) = v;
    }
    __syncthreads();

    // Fused A/C: thread -> (m = tid>>4, o = tid&15)
    {
        const int am = tid >> 4;
        const int ao = tid & 15;
        const float* Sr = &S[am][0];
        float a = 0.f;
        float c = bb[ao];
        #pragma unroll
        for (int h = 0; h < HS_; h++) {
            float qv = Sr[h];
            float kv = Sr[64 + h];
            a += qv * WBs[h * 16 + ao];
            c += qv * WBs[(128 + h) * 16 + ao];
            c += kv * (WBs[(64 + h) * 16 + ao] + WBs[(192 + h) * 16 + ao]);
        }
        g_A[(m0 + am) * OUT_ + ao] = a;
        g_C[(m0 + am) * OUT_ + ao] = c;
    }
}

// ---------------------------------------------------------------------------
// Kernel 3: pair kernel.  TI=4 start-rows per block -> 512 blocks.
// p = b*NPAIR + i*L - i*(i-1)/2 + (j - i)
// ---------------------------------------------------------------------------
__global__ __launch_bounds__(256) void pair_kernel(float* __restrict__ out)
{
    const int b   = blockIdx.y;
    const int i0  = blockIdx.x * 4;
    const int tid = threadIdx.x;

    __shared__ __align__(16) float qs[4 * HS_];
    __shared__ __align__(16) float As[4 * OUT_];

    const int tokbase = b * LL_ + i0;
    qs[tid] = g_q[(size_t)tokbase * HS_ + tid];
    if (tid < 64) As[tid] = g_A[tokbase * OUT_ + tid];
    __syncthreads();

    for (int j = i0 + tid; j < LL_; j += 256) {
        const float4* k4 = (const float4*)(g_k + (size_t)(b * LL_ + j) * HS_);

        float4 d[4];
        #pragma unroll
        for (int ii = 0; ii < 4; ii++) d[ii] = make_float4(0.f, 0.f, 0.f, 0.f);

        #pragma unroll
        for (int half = 0; half < 2; half++) {
            float4 kv[8];
            #pragma unroll
            for (int t = 0; t < 8; t++) kv[t] = k4[half * 8 + t];
            #pragma unroll
            for (int ii = 0; ii < 4; ii++) {
                const float4* q4 = (const float4*)(qs + ii * HS_) + half * 8;
                #pragma unroll
                for (int t = 0; t < 8; t++) {
                    float4 qv = q4[t];
                    d[ii].x += qv.x * kv[t].x;
                    d[ii].y += qv.y * kv[t].y;
                    d[ii].z += qv.z * kv[t].z;
                    d[ii].w += qv.w * kv[t].w;
                }
            }
        }

        float dot[4];
        #pragma unroll
        for (int ii = 0; ii < 4; ii++)
            dot[ii] = (d[ii].x + d[ii].y) + (d[ii].z + d[ii].w);

        const float4* c4 = (const float4*)(g_C + (size_t)(b * LL_ + j) * OUT_);
        float4 cv[4];
        #pragma unroll
        for (int t = 0; t < 4; t++) cv[t] = c4[t];

        #pragma unroll
        for (int ii = 0; ii < 4; ii++) {
            const int i = i0 + ii;
            if (j < i) continue;
            const int poff = i * LL_ - (i * (i - 1)) / 2;
            const int p = b * NPAIR + poff + (j - i);
            float4* o4 = (float4*)(out + (size_t)p * OUT_);
            const float4* a4 = (const float4*)(As + ii * OUT_);
            #pragma unroll
            for (int t = 0; t < 4; t++) {
                float4 av = a4[t];
                float4 r;
                r.x = dot[ii] + av.x + cv[t].x;
                r.y = dot[ii] + av.y + cv[t].y;
                r.z = dot[ii] + av.z + cv[t].z;
                r.w = dot[ii] + av.w + cv[t].w;
                o4[t] = r;
            }
        }
    }
}

// ---------------------------------------------------------------------------
extern "C" void kernel_launch(void* const* d_in, const int* in_sizes, int n_in,
                              void* d_out, int out_size)
{
    const float* x  = (const float*)d_in[0];
    const float* Wq = (const float*)d_in[1];
    const float* bq = (const float*)d_in[2];
    const float* Wk = (const float*)d_in[3];
    const float* bk = (const float*)d_in[4];
    const float* Wb = (const float*)d_in[5];
    const float* bb = (const float*)d_in[6];
    float* out = (float*)d_out;

    proj_kernel<<<dim3(NTOK / BM_, NSPLIT), 256>>>(x, Wq, Wk);
    combine_kernel<<<NTOK / 16, 256>>>(bq, bk, Wb, bb);
    pair_kernel<<<dim3(LL_ / 4, BB_), 256>>>(out);
}

// round 7
// speedup vs baseline: 2.1897x; 1.4031x over previous
#include <cuda_runtime.h>

#define BB_ 4
#define LL_ 512
#define HH_ 768
#define HS_ 64
#define OUT_ 16
#define NTOK (BB_*LL_)          // 2048
#define NPAIR ((LL_*(LL_+1))/2) // 131328
#define NSPLIT 8
#define KSLICE (HH_/NSPLIT)     // 96
#define BK_ 16
#define TILES (KSLICE/BK_)      // 6
#define BM_ 64
#define TI_ 8
#define TJ_ 128

typedef unsigned long long ull;

// f32x2 packed-fp32 helpers (FFMA2 path — PTX-only per SASS_QUICKREF)
__device__ __forceinline__ void fma2(ull& d, ull a, ull b) {
    asm("fma.rn.f32x2 %0, %1, %2, %0;" : "+l"(d) : "l"(a), "l"(b));
}
__device__ __forceinline__ ull dup2(float x) {
    ull r; asm("mov.b64 %0, {%1, %1};" : "=l"(r) : "f"(x)); return r;
}
__device__ __forceinline__ float2 un2(ull v) {
    float2 f; asm("mov.b64 {%0, %1}, %2;" : "=f"(f.x), "=f"(f.y) : "l"(v)); return f;
}

// Scratch (static device globals; no allocations allowed)
__device__ float g_part[NSPLIT][NTOK * 128];  // split-K partials
__device__ float g_q[NTOK * HS_];
__device__ float g_k[NTOK * HS_];
__device__ float g_A[NTOK * OUT_];
__device__ float g_C[NTOK * OUT_];

// ---------------------------------------------------------------------------
// Kernel 1: q|k projection, split-K=8, FFMA2, TM=8 x TN=4, double-buffered.
// ---------------------------------------------------------------------------
__global__ __launch_bounds__(256, 2) void proj_kernel(
    const float* __restrict__ x,
    const float* __restrict__ Wq, const float* __restrict__ Wk)
{
    __shared__ __align__(16) float Xs[2][BM_][BK_];   // 2x4 KB
    __shared__ __align__(16) float Ws[2][BK_][128];   // 2x8 KB

    const int tid   = threadIdx.x;
    const int m0    = blockIdx.x * BM_;
    const int kbase = blockIdx.y * KSLICE;
    const int tx    = tid & 31;
    const int ty    = tid >> 5;

    const int xm = tid >> 2;
    const int xk = (tid & 3) * 4;
    const int wrow0 = tid >> 5;
    const int wcol  = (tid & 31) * 4;
    const float* wsrc = (wcol < 64) ? (Wq + wcol) : (Wk + (wcol - 64));

    float4 xr, wr0, wr1;

    // Preload tile 0 into buffer 0
    xr  = *(const float4*)(x + (size_t)(m0 + xm) * HH_ + kbase + xk);
    wr0 = *(const float4*)(wsrc + (size_t)(kbase + wrow0) * HS_);
    wr1 = *(const float4*)(wsrc + (size_t)(kbase + wrow0 + 8) * HS_);
    *(float4*)(&Xs[0][xm][xk]) = xr;
    *(float4*)(&Ws[0][wrow0][wcol])     = wr0;
    *(float4*)(&Ws[0][wrow0 + 8][wcol]) = wr1;
    __syncthreads();

    ull acc[8][2];
    #pragma unroll
    for (int r = 0; r < 8; r++) { acc[r][0] = 0ull; acc[r][1] = 0ull; }

    for (int t = 0; t < TILES; t++) {
        const int cur = t & 1;
        if (t + 1 < TILES) {
            const int k0n = kbase + (t + 1) * BK_;
            xr  = *(const float4*)(x + (size_t)(m0 + xm) * HH_ + k0n + xk);
            wr0 = *(const float4*)(wsrc + (size_t)(k0n + wrow0) * HS_);
            wr1 = *(const float4*)(wsrc + (size_t)(k0n + wrow0 + 8) * HS_);
        }

        #pragma unroll
        for (int g = 0; g < BK_ / 4; g++) {
            float4 xf[8];
            #pragma unroll
            for (int r = 0; r < 8; r++)
                xf[r] = *(const float4*)(&Xs[cur][ty * 8 + r][g * 4]);
            #pragma unroll
            for (int dk = 0; dk < 4; dk++) {
                float4 wv = *(const float4*)(&Ws[cur][g * 4 + dk][tx * 4]);
                ull w0, w1;
                asm("mov.b64 %0, {%1, %2};" : "=l"(w0) : "f"(wv.x), "f"(wv.y));
                asm("mov.b64 %0, {%1, %2};" : "=l"(w1) : "f"(wv.z), "f"(wv.w));
                #pragma unroll
                for (int r = 0; r < 8; r++) {
                    const float* xp = (const float*)&xf[r];
                    ull xd = dup2(xp[dk]);
                    fma2(acc[r][0], xd, w0);
                    fma2(acc[r][1], xd, w1);
                }
            }
        }

        if (t + 1 < TILES) {
            const int nxt = 1 - cur;
            *(float4*)(&Xs[nxt][xm][xk]) = xr;
            *(float4*)(&Ws[nxt][wrow0][wcol])     = wr0;
            *(float4*)(&Ws[nxt][wrow0 + 8][wcol]) = wr1;
            __syncthreads();
        }
    }

    float* dst = g_part[blockIdx.y];
    #pragma unroll
    for (int r = 0; r < 8; r++) {
        float2 lo = un2(acc[r][0]), hi = un2(acc[r][1]);
        float4 v = make_float4(lo.x, lo.y, hi.x, hi.y);
        *(float4*)(dst + (size_t)(m0 + ty * 8 + r) * 128 + tx * 4) = v;
    }
}

// ---------------------------------------------------------------------------
// Kernel 2: combine 8 split-K partials + bias -> g_q/g_k, then fused A/C.
// ---------------------------------------------------------------------------
__global__ __launch_bounds__(256) void combine_kernel(
    const float* __restrict__ bq, const float* __restrict__ bk,
    const float* __restrict__ Wb, const float* __restrict__ bb)
{
    __shared__ __align__(16) float S[16][128];
    __shared__ __align__(16) float WBs[256 * 16];

    const int tid = threadIdx.x;
    const int m0  = blockIdx.x * 16;

    {
        const float4* src = (const float4*)Wb;
        float4* dst = (float4*)WBs;
        #pragma unroll
        for (int t = 0; t < 4; t++) dst[tid + 256 * t] = src[tid + 256 * t];
    }

    const size_t base4 = (size_t)m0 * 32;
    #pragma unroll
    for (int e = 0; e < 2; e++) {
        const int idx = tid + 256 * e;
        const int m   = idx >> 5;
        const int n   = (idx & 31) * 4;
        float4 v = ((const float4*)g_part[0])[base4 + idx];
        #pragma unroll
        for (int s = 1; s < NSPLIT; s++) {
            float4 p = ((const float4*)g_part[s])[base4 + idx];
            v.x += p.x; v.y += p.y; v.z += p.z; v.w += p.w;
        }
        float4 bias = (n < 64) ? *(const float4*)(bq + n)
                               : *(const float4*)(bk + (n - 64));
        v.x += bias.x; v.y += bias.y; v.z += bias.z; v.w += bias.w;
        if (n < 64) *(float4*)(g_q + (size_t)(m0 + m) * HS_ + n)        = v;
        else        *(float4*)(g_k + (size_t)(m0 + m) * HS_ + (n - 64)) = v;
        *(float4*)(&S[m][n]) = v;
    }
    __syncthreads();

    {
        const int am = tid >> 4;
        const int ao = tid & 15;
        const float* Sr = &S[am][0];
        float a = 0.f;
        float c = bb[ao];
        #pragma unroll
        for (int h = 0; h < HS_; h++) {
            float qv = Sr[h];
            float kv = Sr[64 + h];
            a += qv * WBs[h * 16 + ao];
            c += qv * WBs[(128 + h) * 16 + ao];
            c += kv * (WBs[(64 + h) * 16 + ao] + WBs[(192 + h) * 16 + ao]);
        }
        g_A[(m0 + am) * OUT_ + ao] = a;
        g_C[(m0 + am) * OUT_ + ao] = c;
    }
}

// ---------------------------------------------------------------------------
// Kernel 3: tiled pair kernel.  Block = one (i-tile 8, j-tile 128) tile.
// Tiles per batch: groups g=i0>>7 get (4-g) j-tiles -> 160 tiles/batch.
// Stage k/C tiles in SMEM (coalesced), rotation-swizzled k rows; compute
// S[8][128] dot matrix; store phase: warp=ii row, lanes write consecutive
// float4 -> perfectly coalesced 512B STG wavefronts.
// ---------------------------------------------------------------------------
__global__ __launch_bounds__(256) void pair_kernel(float* __restrict__ out)
{
    __shared__ __align__(16) float4 ks4[TJ_][16];   // 32 KB (rotated cols)
    __shared__ __align__(16) float4 C4s[TJ_ * 4];   // 8 KB
    __shared__ __align__(16) float4 qs4[TI_ * 16];  // 2 KB
    __shared__ __align__(16) float4 A4s[TI_ * 4];   // 512 B
    __shared__ float Sd[TI_][TJ_];                  // 4 KB

    const int b   = blockIdx.y;
    const int tid = threadIdx.x;

    // Decode tile id -> (i0, j0)
    int id = blockIdx.x;
    int g, local;
    if      (id < 64)  { g = 0; local = id; }
    else if (id < 112) { g = 1; local = id - 64; }
    else if (id < 144) { g = 2; local = id - 112; }
    else               { g = 3; local = id - 144; }
    const int per = 4 - g;
    const int i0b = 16 * g + local / per;
    const int jt  = local % per;
    const int i0  = i0b * TI_;
    const int j0  = (g + jt) * TJ_;

    // ---- Stage tiles ----
    const float4* kg = (const float4*)(g_k + (size_t)(b * LL_ + j0) * HS_);
    #pragma unroll
    for (int e = 0; e < 8; e++) {
        const int idx = tid + 256 * e;
        const int r = idx >> 4, c = idx & 15;
        ks4[r][(c + r) & 15] = kg[idx];
    }
    const float4* cg = (const float4*)(g_C + (size_t)(b * LL_ + j0) * OUT_);
    C4s[tid]       = cg[tid];
    C4s[tid + 256] = cg[tid + 256];
    if (tid < 128) qs4[tid] = ((const float4*)(g_q + (size_t)(b * LL_ + i0) * HS_))[tid];
    if (tid < 32)  A4s[tid] = ((const float4*)(g_A + (size_t)(b * LL_ + i0) * OUT_))[tid];
    __syncthreads();

    // ---- Compute S[8][128]: thread -> (ii2 = tid>>6: rows 2ii2,2ii2+1;
    //      jj2 = tid&63: cols jj2, jj2+64) ----
    {
        const int jj2 = tid & 63;
        const int ii2 = tid >> 6;
        const int ra = jj2, rb = jj2 + 64;

        float4 d00 = make_float4(0,0,0,0), d01 = d00, d10 = d00, d11 = d00;
        #pragma unroll
        for (int c = 0; c < 16; c++) {
            float4 ka = ks4[ra][(c + ra) & 15];
            float4 kb = ks4[rb][(c + rb) & 15];
            float4 qa = qs4[(2 * ii2 + 0) * 16 + c];
            float4 qb = qs4[(2 * ii2 + 1) * 16 + c];
            d00.x += qa.x*ka.x; d00.y += qa.y*ka.y; d00.z += qa.z*ka.z; d00.w += qa.w*ka.w;
            d01.x += qa.x*kb.x; d01.y += qa.y*kb.y; d01.z += qa.z*kb.z; d01.w += qa.w*kb.w;
            d10.x += qb.x*ka.x; d10.y += qb.y*ka.y; d10.z += qb.z*ka.z; d10.w += qb.w*ka.w;
            d11.x += qb.x*kb.x; d11.y += qb.y*kb.y; d11.z += qb.z*kb.z; d11.w += qb.w*kb.w;
        }
        Sd[2*ii2+0][ra] = (d00.x + d00.y) + (d00.z + d00.w);
        Sd[2*ii2+0][rb] = (d01.x + d01.y) + (d01.z + d01.w);
        Sd[2*ii2+1][ra] = (d10.x + d10.y) + (d10.z + d10.w);
        Sd[2*ii2+1][rb] = (d11.x + d11.y) + (d11.z + d11.w);
    }
    __syncthreads();

    // ---- Store phase: warp w -> row ii=w; lanes write consecutive float4 ----
    {
        const int ii   = tid >> 5;
        const int lane = tid & 31;
        const int i    = i0 + ii;
        const int poff = i * LL_ - (i * (i - 1)) / 2;
        const int o4   = lane & 3;
        const float4 av = A4s[ii * 4 + o4];
        // out float4 base for (i, j0): index of pair (i,j0) * 4
        float4* ob = (float4*)out + ((size_t)b * NPAIR + poff + (j0 - i)) * 4;

        #pragma unroll
        for (int it = 0; it < 16; it++) {
            const int idx  = lane + 32 * it;
            const int pair = idx >> 2;
            if (j0 + pair >= i) {
                const float dot = Sd[ii][pair];
                const float4 cv = C4s[idx];
                float4 r;
                r.x = dot + av.x + cv.x;
                r.y = dot + av.y + cv.y;
                r.z = dot + av.z + cv.z;
                r.w = dot + av.w + cv.w;
                ob[idx] = r;
            }
        }
    }
}

// ---------------------------------------------------------------------------
extern "C" void kernel_launch(void* const* d_in, const int* in_sizes, int n_in,
                              void* d_out, int out_size)
{
    const float* x  = (const float*)d_in[0];
    const float* Wq = (const float*)d_in[1];
    const float* bq = (const float*)d_in[2];
    const float* Wk = (const float*)d_in[3];
    const float* bk = (const float*)d_in[4];
    const float* Wb = (const float*)d_in[5];
    const float* bb = (const float*)d_in[6];
    float* out = (float*)d_out;

    proj_kernel<<<dim3(NTOK / BM_, NSPLIT), 256>>>(x, Wq, Wk);
    combine_kernel<<<NTOK / 16, 256>>>(bq, bk, Wb, bb);
    pair_kernel<<<dim3(160, BB_), 256>>>(out);
}